// round 1
// baseline (speedup 1.0000x reference)
#include <cuda_runtime.h>

#define EMBED 128
#define ATTR 25
#define REM 28
#define TOTAL_ROWS 77   // 50 level + 2 type + 2 feature + 3 exchange + 20 pair

// Projected tables: g_P[r][e] = sum_k tab_r[k] * W[e][off_r + k]  (+ b[e] folded into pair rows)
__device__ float g_P[TOTAL_ROWS * EMBED];

__global__ void precompute_kernel(const float* __restrict__ level_tab,
                                  const float* __restrict__ type_tab,
                                  const float* __restrict__ feature_tab,
                                  const float* __restrict__ exchange_tab,
                                  const float* __restrict__ pair_tab,
                                  const float* __restrict__ W,
                                  const float* __restrict__ b) {
    int r = blockIdx.x;      // 0..76
    int e = threadIdx.x;     // 0..127
    const float* tab;
    int off, dim;
    bool add_b = false;
    if (r < 50)      { tab = level_tab    + r * ATTR;        off = 0;   dim = ATTR; }
    else if (r < 52) { tab = type_tab     + (r - 50) * ATTR; off = 25;  dim = ATTR; }
    else if (r < 54) { tab = feature_tab  + (r - 52) * ATTR; off = 50;  dim = ATTR; }
    else if (r < 57) { tab = exchange_tab + (r - 54) * ATTR; off = 75;  dim = ATTR; }
    else             { tab = pair_tab     + (r - 57) * REM;  off = 100; dim = REM; add_b = true; }

    float s = add_b ? b[e] : 0.0f;
    const float* wrow = W + e * EMBED + off;
    #pragma unroll 4
    for (int k = 0; k < dim; k++) s += tab[k] * wrow[k];
    g_P[r * EMBED + e] = s;
}

// Warp-per-row: lane owns one float4 (4 of the 128 outputs).
__global__ void __launch_bounds__(256) gather_sum_kernel(const int* __restrict__ level_idx,
                                                         const int* __restrict__ type_idx,
                                                         const int* __restrict__ feature_idx,
                                                         const int* __restrict__ exchange_idx,
                                                         const int* __restrict__ pair_idx,
                                                         float4* __restrict__ out,
                                                         int n) {
    __shared__ float4 sP[TOTAL_ROWS * (EMBED / 4)];   // 77 * 32 float4 = 39424 B
    const float4* gP4 = reinterpret_cast<const float4*>(g_P);
    for (int i = threadIdx.x; i < TOTAL_ROWS * (EMBED / 4); i += blockDim.x)
        sP[i] = gP4[i];
    __syncthreads();

    const int lane   = threadIdx.x & 31;
    const int warp   = (blockIdx.x * blockDim.x + threadIdx.x) >> 5;
    const int nwarps = (gridDim.x * blockDim.x) >> 5;

    for (int r = warp; r < n; r += nwarps) {
        int l  = level_idx[r];
        int t  = type_idx[r];
        int f  = feature_idx[r];
        int x  = exchange_idx[r];
        int p  = pair_idx[r];

        float4 a = sP[l * 32 + lane];
        float4 v = sP[(50 + t) * 32 + lane];
        float4 g = sP[(52 + f) * 32 + lane];
        float4 h = sP[(54 + x) * 32 + lane];
        float4 q = sP[(57 + p) * 32 + lane];   // has b folded in

        float4 s;
        s.x = a.x + v.x + g.x + h.x + q.x;
        s.y = a.y + v.y + g.y + h.y + q.y;
        s.z = a.z + v.z + g.z + h.z + q.z;
        s.w = a.w + v.w + g.w + h.w + q.w;

        out[(size_t)r * 32 + lane] = s;
    }
}

extern "C" void kernel_launch(void* const* d_in, const int* in_sizes, int n_in,
                              void* d_out, int out_size) {
    const float* level_tab    = (const float*)d_in[0];
    const float* type_tab     = (const float*)d_in[1];
    const float* feature_tab  = (const float*)d_in[2];
    const float* exchange_tab = (const float*)d_in[3];
    const float* pair_tab     = (const float*)d_in[4];
    const float* W            = (const float*)d_in[5];
    const float* b            = (const float*)d_in[6];
    const int* level_idx      = (const int*)d_in[7];
    const int* type_idx       = (const int*)d_in[8];
    const int* feature_idx    = (const int*)d_in[9];
    const int* exchange_idx   = (const int*)d_in[10];
    const int* pair_idx       = (const int*)d_in[11];

    int n = in_sizes[7];   // N rows

    precompute_kernel<<<TOTAL_ROWS, EMBED>>>(level_tab, type_tab, feature_tab,
                                             exchange_tab, pair_tab, W, b);

    // 148 SMs * 8 blocks, 256 thr (8 warps) each -> 9472 warps grid-striding rows
    gather_sum_kernel<<<1184, 256>>>(level_idx, type_idx, feature_idx,
                                     exchange_idx, pair_idx,
                                     (float4*)d_out, n);
}

// round 2
// speedup vs baseline: 1.4564x; 1.4564x over previous
#include <cuda_runtime.h>

#define EMBED 128
#define ATTR 25
#define REM 28
#define NROWS_P 77        // 50 level + 2 type + 2 feature + 3 exchange + 20 pair
#define NCOMB 240         // 2*2*3*20 combined (type,feature,exchange,pair)
#define SMEM_BYTES ((50 + NCOMB) * EMBED * 4)   // 148480 B

// Stage 1 output: per-source projected rows. b folded into pair rows.
__device__ float g_P[NROWS_P * EMBED];
// Stage 2 output: combined type/feature/exchange/pair rows (b included).
__device__ float g_C[NCOMB * EMBED];

__global__ void precompute_kernel(const float* __restrict__ level_tab,
                                  const float* __restrict__ type_tab,
                                  const float* __restrict__ feature_tab,
                                  const float* __restrict__ exchange_tab,
                                  const float* __restrict__ pair_tab,
                                  const float* __restrict__ W,
                                  const float* __restrict__ b) {
    int r = blockIdx.x;      // 0..76
    int e = threadIdx.x;     // 0..127
    const float* tab;
    int off, dim;
    bool add_b = false;
    if (r < 50)      { tab = level_tab    + r * ATTR;        off = 0;   dim = ATTR; }
    else if (r < 52) { tab = type_tab     + (r - 50) * ATTR; off = 25;  dim = ATTR; }
    else if (r < 54) { tab = feature_tab  + (r - 52) * ATTR; off = 50;  dim = ATTR; }
    else if (r < 57) { tab = exchange_tab + (r - 54) * ATTR; off = 75;  dim = ATTR; }
    else             { tab = pair_tab     + (r - 57) * REM;  off = 100; dim = REM; add_b = true; }

    float s = add_b ? b[e] : 0.0f;
    const float* wrow = W + e * EMBED + off;
    #pragma unroll 4
    for (int k = 0; k < dim; k++) s += tab[k] * wrow[k];
    g_P[r * EMBED + e] = s;
}

// Combine type×feature×exchange×pair into 240 rows: c = ((t*2+f)*3+x)*20+p
__global__ void combine_kernel() {
    int c = blockIdx.x;      // 0..239
    int e = threadIdx.x;     // 0..127
    int p = c % 20;
    int x = (c / 20) % 3;
    int f = (c / 60) % 2;
    int t = c / 120;
    g_C[c * EMBED + e] = g_P[(50 + t) * EMBED + e]
                       + g_P[(52 + f) * EMBED + e]
                       + g_P[(54 + x) * EMBED + e]
                       + g_P[(57 + p) * EMBED + e];   // b already folded into pair rows
}

// Warp-per-row, 4 rows per iteration. Lane owns one float4 of the 128-wide output.
// smem: [0..49] level rows, [50..289] combined rows (float4 granularity: 32 per row).
__global__ void __launch_bounds__(1024) gather_sum_kernel(const int* __restrict__ level_idx,
                                                          const int* __restrict__ type_idx,
                                                          const int* __restrict__ feature_idx,
                                                          const int* __restrict__ exchange_idx,
                                                          const int* __restrict__ pair_idx,
                                                          float4* __restrict__ out,
                                                          int n) {
    extern __shared__ float4 sP[];   // (50+240)*32 float4
    const float4* gL4 = reinterpret_cast<const float4*>(g_P);  // rows 0..49 are level
    const float4* gC4 = reinterpret_cast<const float4*>(g_C);
    for (int i = threadIdx.x; i < 50 * 32; i += blockDim.x) sP[i] = gL4[i];
    for (int i = threadIdx.x; i < NCOMB * 32; i += blockDim.x) sP[50 * 32 + i] = gC4[i];
    __syncthreads();

    const int lane   = threadIdx.x & 31;
    const int warp   = (blockIdx.x * blockDim.x + threadIdx.x) >> 5;
    const int nwarps = (gridDim.x * blockDim.x) >> 5;

    int r = warp * 4;
    const int stride = nwarps * 4;

    for (; r + 3 < n; r += stride) {
        // 4 rows of indices per idx array, one 16B broadcast load each
        int4 L = *reinterpret_cast<const int4*>(level_idx + r);
        int4 T = *reinterpret_cast<const int4*>(type_idx + r);
        int4 F = *reinterpret_cast<const int4*>(feature_idx + r);
        int4 X = *reinterpret_cast<const int4*>(exchange_idx + r);
        int4 P = *reinterpret_cast<const int4*>(pair_idx + r);

        int l[4] = {L.x, L.y, L.z, L.w};
        int t[4] = {T.x, T.y, T.z, T.w};
        int f[4] = {F.x, F.y, F.z, F.w};
        int x[4] = {X.x, X.y, X.z, X.w};
        int p[4] = {P.x, P.y, P.z, P.w};

        #pragma unroll
        for (int k = 0; k < 4; k++) {
            int c = ((t[k] * 2 + f[k]) * 3 + x[k]) * 20 + p[k];
            float4 a = sP[l[k] * 32 + lane];
            float4 q = sP[(50 + c) * 32 + lane];
            float4 s;
            s.x = a.x + q.x; s.y = a.y + q.y; s.z = a.z + q.z; s.w = a.w + q.w;
            out[(size_t)(r + k) * 32 + lane] = s;
        }
    }
    // tail (n not multiple of 4·stride alignment)
    for (; r < n; r++) {
        int c = ((type_idx[r] * 2 + feature_idx[r]) * 3 + exchange_idx[r]) * 20 + pair_idx[r];
        float4 a = sP[level_idx[r] * 32 + lane];
        float4 q = sP[(50 + c) * 32 + lane];
        float4 s;
        s.x = a.x + q.x; s.y = a.y + q.y; s.z = a.z + q.z; s.w = a.w + q.w;
        out[(size_t)r * 32 + lane] = s;
    }
}

extern "C" void kernel_launch(void* const* d_in, const int* in_sizes, int n_in,
                              void* d_out, int out_size) {
    const float* level_tab    = (const float*)d_in[0];
    const float* type_tab     = (const float*)d_in[1];
    const float* feature_tab  = (const float*)d_in[2];
    const float* exchange_tab = (const float*)d_in[3];
    const float* pair_tab     = (const float*)d_in[4];
    const float* W            = (const float*)d_in[5];
    const float* b            = (const float*)d_in[6];
    const int* level_idx      = (const int*)d_in[7];
    const int* type_idx       = (const int*)d_in[8];
    const int* feature_idx    = (const int*)d_in[9];
    const int* exchange_idx   = (const int*)d_in[10];
    const int* pair_idx       = (const int*)d_in[11];

    int n = in_sizes[7];   // N rows

    cudaFuncSetAttribute(gather_sum_kernel,
                         cudaFuncAttributeMaxDynamicSharedMemorySize, SMEM_BYTES);

    precompute_kernel<<<NROWS_P, EMBED>>>(level_tab, type_tab, feature_tab,
                                          exchange_tab, pair_tab, W, b);
    combine_kernel<<<NCOMB, EMBED>>>();

    // 148 blocks × 1024 threads = 4736 warps, one resident wave (145 KB smem/block)
    gather_sum_kernel<<<148, 1024, SMEM_BYTES>>>(level_idx, type_idx, feature_idx,
                                                 exchange_idx, pair_idx,
                                                 (float4*)d_out, n);
}

// round 3
// speedup vs baseline: 1.5701x; 1.0781x over previous
#include <cuda_runtime.h>

#define EMBED 128
#define ATTR 25
#define REM 28
#define NLEVEL 50
#define NPROJ 77          // 50 level + 2 type + 2 feature + 3 exchange + 20 pair
#define NTEMP 27          // non-level projected rows
#define NCOMB 240         // 2*2*3*20 combined rows

// smem layout (floats):
//   [0, 6400)            : 50 level projected rows
//   [6400, 9856)         : 27 temp projected rows (type/feature/exchange/pair)
//   [9856, 40576)        : 240 combined rows (first 16384 floats double as W^T during phase A)
#define F_TEMP  (NLEVEL * EMBED)            // 6400
#define F_COMB  (F_TEMP + NTEMP * EMBED)    // 9856
#define SMEM_FLOATS (F_COMB + NCOMB * EMBED)  // 40576
#define SMEM_BYTES  (SMEM_FLOATS * 4)         // 162304

__global__ void __launch_bounds__(1024, 1)
fused_embed_kernel(const float* __restrict__ level_tab,
                   const float* __restrict__ type_tab,
                   const float* __restrict__ feature_tab,
                   const float* __restrict__ exchange_tab,
                   const float* __restrict__ pair_tab,
                   const float* __restrict__ W,
                   const float* __restrict__ b,
                   const int* __restrict__ level_idx,
                   const int* __restrict__ type_idx,
                   const int* __restrict__ feature_idx,
                   const int* __restrict__ exchange_idx,
                   const int* __restrict__ pair_idx,
                   float4* __restrict__ out, int n)
{
    extern __shared__ float sm[];

    // ---- Phase 0: load W transposed into the (future) combined region.
    // sWt[k*128 + e] = W[e*128 + k]  -> phase-A reads are bank-conflict-free.
    float* sWt = sm + F_COMB;
    for (int i = threadIdx.x; i < EMBED * EMBED; i += 1024) {
        int e = i >> 7, k = i & 127;
        sWt[k * EMBED + e] = W[i];
    }
    __syncthreads();

    // ---- Phase A: 77 projected rows. b folded into pair rows.
    for (int i = threadIdx.x; i < NPROJ * EMBED; i += 1024) {
        int r = i >> 7, e = i & 127;   // warp lanes span consecutive e, same r
        const float* tab; int off, dim; float s = 0.0f;
        if (r < 50)      { tab = level_tab    + r * ATTR;        off = 0;   dim = ATTR; }
        else if (r < 52) { tab = type_tab     + (r - 50) * ATTR; off = 25;  dim = ATTR; }
        else if (r < 54) { tab = feature_tab  + (r - 52) * ATTR; off = 50;  dim = ATTR; }
        else if (r < 57) { tab = exchange_tab + (r - 54) * ATTR; off = 75;  dim = ATTR; }
        else             { tab = pair_tab     + (r - 57) * REM;  off = 100; dim = REM; s = b[e]; }
        #pragma unroll 5
        for (int k = 0; k < dim; k++)
            s += tab[k] * sWt[(off + k) * EMBED + e];   // tab[k] broadcast, sWt conflict-free
        if (r < 50) sm[r * EMBED + e] = s;
        else        sm[F_TEMP + (r - 50) * EMBED + e] = s;
    }
    __syncthreads();

    // ---- Phase B: 240 combined rows (overwrites the W^T overlay; reads only sTemp).
    {
        float4* sm4 = reinterpret_cast<float4*>(sm);
        const float4* sT4 = reinterpret_cast<const float4*>(sm + F_TEMP);
        float4* sC4 = sm4 + (F_COMB / 4);
        for (int i = threadIdx.x; i < NCOMB * 32; i += 1024) {
            int c = i >> 5, v = i & 31;
            int p = c % 20, x = (c / 20) % 3, f = (c / 60) % 2, t = c / 120;
            float4 a  = sT4[t * 32 + v];          // type
            float4 bb = sT4[(2 + f) * 32 + v];    // feature
            float4 cc = sT4[(4 + x) * 32 + v];    // exchange
            float4 dd = sT4[(7 + p) * 32 + v];    // pair (+b)
            float4 s;
            s.x = a.x + bb.x + cc.x + dd.x;
            s.y = a.y + bb.y + cc.y + dd.y;
            s.z = a.z + bb.z + cc.z + dd.z;
            s.w = a.w + bb.w + cc.w + dd.w;
            sC4[c * 32 + v] = s;
        }
    }
    __syncthreads();

    // ---- Phase C: stream. Warp per row, 4 rows per iteration, lane owns one float4.
    const int lane   = threadIdx.x & 31;
    const int warp   = (blockIdx.x * 1024 + threadIdx.x) >> 5;
    const int nwarps = (gridDim.x * 1024) >> 5;
    const float4* sL4 = reinterpret_cast<const float4*>(sm);
    const float4* sC4 = reinterpret_cast<const float4*>(sm) + (F_COMB / 4);

    int r = warp * 4;
    const int stride = nwarps * 4;

    for (; r + 3 < n; r += stride) {
        int4 L = *reinterpret_cast<const int4*>(level_idx + r);
        int4 T = *reinterpret_cast<const int4*>(type_idx + r);
        int4 F = *reinterpret_cast<const int4*>(feature_idx + r);
        int4 X = *reinterpret_cast<const int4*>(exchange_idx + r);
        int4 P = *reinterpret_cast<const int4*>(pair_idx + r);

        int l[4] = {L.x, L.y, L.z, L.w};
        int t[4] = {T.x, T.y, T.z, T.w};
        int f[4] = {F.x, F.y, F.z, F.w};
        int x[4] = {X.x, X.y, X.z, X.w};
        int p[4] = {P.x, P.y, P.z, P.w};

        #pragma unroll
        for (int k = 0; k < 4; k++) {
            int c = ((t[k] * 2 + f[k]) * 3 + x[k]) * 20 + p[k];
            float4 a = sL4[l[k] * 32 + lane];
            float4 q = sC4[c * 32 + lane];
            float4 s;
            s.x = a.x + q.x; s.y = a.y + q.y; s.z = a.z + q.z; s.w = a.w + q.w;
            __stcs(out + (size_t)(r + k) * 32 + lane, s);   // streaming store
        }
    }
    for (; r < n; r++) {   // tail
        int c = ((type_idx[r] * 2 + feature_idx[r]) * 3 + exchange_idx[r]) * 20 + pair_idx[r];
        float4 a = sL4[level_idx[r] * 32 + lane];
        float4 q = sC4[c * 32 + lane];
        float4 s;
        s.x = a.x + q.x; s.y = a.y + q.y; s.z = a.z + q.z; s.w = a.w + q.w;
        out[(size_t)r * 32 + lane] = s;
    }
}

extern "C" void kernel_launch(void* const* d_in, const int* in_sizes, int n_in,
                              void* d_out, int out_size) {
    const float* level_tab    = (const float*)d_in[0];
    const float* type_tab     = (const float*)d_in[1];
    const float* feature_tab  = (const float*)d_in[2];
    const float* exchange_tab = (const float*)d_in[3];
    const float* pair_tab     = (const float*)d_in[4];
    const float* W            = (const float*)d_in[5];
    const float* b            = (const float*)d_in[6];
    const int* level_idx      = (const int*)d_in[7];
    const int* type_idx       = (const int*)d_in[8];
    const int* feature_idx    = (const int*)d_in[9];
    const int* exchange_idx   = (const int*)d_in[10];
    const int* pair_idx       = (const int*)d_in[11];

    int n = in_sizes[7];   // N rows

    int sm_count = 148;
    cudaDeviceGetAttribute(&sm_count, cudaDevAttrMultiProcessorCount, 0);

    cudaFuncSetAttribute(fused_embed_kernel,
                         cudaFuncAttributeMaxDynamicSharedMemorySize, SMEM_BYTES);

    // Exactly one resident wave: 1 block/SM (162 KB smem), 1024 threads.
    fused_embed_kernel<<<sm_count, 1024, SMEM_BYTES>>>(
        level_tab, type_tab, feature_tab, exchange_tab, pair_tab, W, b,
        level_idx, type_idx, feature_idx, exchange_idx, pair_idx,
        (float4*)d_out, n);
}